// round 17
// baseline (speedup 1.0000x reference)
#include <cuda_runtime.h>
#include <cuda_fp16.h>
#include <cstdint>

// Shapes
#define NB 256
#define NF 8
#define NS 200
#define ND 64
#define NH 36
#define NBF (NB*NF)          // 2048
#define NSTAT (NF*NH)        // 288
#define EPS_V 1e-3f

#define NTILES 400           // tiles of 128 rows over NB*NS=51200 rows per f
#define P1T 128
#define P1GRID (NF*NTILES)   // 3200

// ---- pass1 shared memory (float indices) ----
// A_s:   [0,3072)       [k=64][quarter=4][12] (cols 9..11 zero)
// qh_s:  [3072,3152)    [2][4 quarters][10]
// kt0:   [3200,5264)    key chunk buf0 [16][129]
// kt1:   [5264,7328)    key chunk buf1 [16][129]
// h_st:  overlays [0,4864)  h staging [128][38] (A/qh/kt0 dead by then)
#define SM_A 0
#define SM_QH 3072
#define SM_KT0 3200
#define SM_KT1 5264
#define KTP 129
#define KCH 16                // k-chunk
#define HPAD 38
#define P1_SMEM_FLOATS 7328
#define P1_SMEM_BYTES  (P1_SMEM_FLOATS*4)          // 29312

// Scratch (no allocs -> device globals)
__device__ __half2 g_h[(size_t)NBF * (NS * NH / 2)];   // fp16 hidden acts
__device__ float g_A  [NF * 3072];                     // prepped A, pass1 layout
__device__ float g_qh [NBF * NH];                      // prepped qh
__device__ float g_psum[P1GRID * NH];
__device__ float g_psq [P1GRID * NH];
__device__ float g_mean[NSTAT];
__device__ float g_inv [NSTAT];

union F4U2 { float4 f4; ulonglong2 u2; };
union F2U1 { float2 f2; unsigned long long u; };

__device__ __forceinline__ unsigned long long pack2(float x) {
    unsigned long long r;
    asm("mov.b64 %0, {%1, %1};" : "=l"(r) : "f"(x));
    return r;
}
__device__ __forceinline__ void fma2(unsigned long long &acc,
                                     unsigned long long a,
                                     unsigned long long b) {
    asm("fma.rn.f32x2 %0, %1, %2, %0;" : "+l"(acc) : "l"(a), "l"(b));
}

// FFMA-only sigmoid (no MUFU pressure)
__device__ __forceinline__ float fast_sigmoid(float z) {
    float x = -z * 1.4426950408889634f;
    x = fminf(fmaxf(x, -30.0f), 30.0f);
    float n = rintf(x);
    float fr = x - n;
    float p = 0.0013333558f;
    p = fmaf(p, fr, 0.009618129f);
    p = fmaf(p, fr, 0.055504109f);
    p = fmaf(p, fr, 0.24022651f);
    p = fmaf(p, fr, 0.69314718f);
    p = fmaf(p, fr, 1.0f);
    float sc = __int_as_float(((int)n + 127) << 23);
    float e = p * sc;                 // exp(-z)
    float w = 1.0f + e;
    float r = __int_as_float(0x7EF311C3 - __float_as_int(w));
    r = r * (2.0f - w * r);
    r = r * (2.0f - w * r);
    return r;
}

// ---------------------------------------------------------------------------
// Prep: A (per f) and qh (per b,f) computed ONCE.
// ---------------------------------------------------------------------------
__global__ void __launch_bounds__(256) prep_kernel(
    const float* __restrict__ q, const float* __restrict__ W_h,
    const float* __restrict__ b_h)
{
    const int bid = blockIdx.x;
    const int t = threadIdx.x;
    if (bid < NBF) {
        __shared__ float ws[2304];      // [k=64][j=36] W_q+W_d
        __shared__ float qv[64];
        const int f = bid & 7;
        const float* Wf = W_h + f * (3 * ND * NH);
        for (int i = t; i < 2304; i += 256)
            ws[i] = Wf[ND * NH + i] + Wf[2 * ND * NH + i];
        if (t < 64) qv[t] = q[(size_t)bid * ND + t];
        __syncthreads();
        if (t < NH) {
            float s = b_h[f * NH + t];
            #pragma unroll 8
            for (int k = 0; k < ND; ++k)
                s = fmaf(qv[k], ws[k * NH + t], s);
            g_qh[bid * NH + t] = s;
        }
    } else {
        const int f = bid - NBF;
        const float* Wf = W_h + f * (3 * ND * NH);
        for (int i = t; i < 3072; i += 256) {
            int k = i / 48, c = i - k * 48;
            int qq = c / 12, cc = c - qq * 12;
            float v = 0.0f;
            if (cc < 9) {
                int j = qq * 9 + cc;
                v = Wf[k * NH + j] - Wf[(2 * ND + k) * NH + j];
            }
            g_A[f * 3072 + i] = v;
        }
    }
}

// ---------------------------------------------------------------------------
// Pass 1: per-CTA 128-row tile of K_f @ A_f. 4 k-chunks of 16, double-buffered
// smem with register prefetch (LDG of chunk c+1 overlaps FMA of chunk c).
// Warp = 9-col quarter; lane = rows {l,l+32,l+64,l+96}. Stats via shfl.
// ---------------------------------------------------------------------------
__global__ void __launch_bounds__(P1T, 6) pass1_kernel(
    const float* __restrict__ key)
{
    extern __shared__ float sm[];
    float* A_s   = sm + SM_A;     // [64][48]
    float* qh_sm = sm + SM_QH;    // [2][4][10]
    float* kt0   = sm + SM_KT0;   // [16][129]
    float* kt1   = sm + SM_KT1;   // [16][129]
    float* h_st  = sm;            // overlay: [128][38]

    const int t = threadIdx.x;
    const int wq = t >> 5;        // warp = col quarter (cols 9*wq .. 9*wq+8)
    const int l  = t & 31;
    const int f    = blockIdx.x / NTILES;
    const int tile = blockIdx.x - f * NTILES;
    const int g0 = tile * 128;
    const int b0 = g0 / NS;

    // A: coalesced copy from g_A
    {
        const float4* ga = (const float4*)(g_A + f * 3072);
        float4* as4 = (float4*)A_s;
        #pragma unroll
        for (int it = 0; it < 6; ++it)
            as4[t + it * P1T] = ga[t + it * P1T];
    }
    // qh: 1 LDG per thread (72 threads)
    if (t < 72) {
        int bb = t / 36, j = t - bb * 36;
        int b = b0 + bb; if (b > NB - 1) b = NB - 1;
        int qq = j / 9, cc = j - qq * 9;
        qh_sm[bb * 40 + qq * 10 + cc] = g_qh[(b * NF + f) * NH + j];
    }

    // per-thread persistent key pointers: thread = (rbase = t>>2, c4l = t&3),
    // rows rbase+32*it, float4 column index ch*4 + c4l.
    const int c4l   = t & 3;
    const int rbase = t >> 2;
    const float4* gp0; const float4* gp1; const float4* gp2; const float4* gp3;
    {
        const float4* kg = (const float4*)key;
        int g, b, s;
        g = g0 + rbase;       b = g / NS; s = g - b * NS;
        gp0 = kg + ((size_t)(b * NF + f) * NS + s) * 16 + c4l;
        g = g0 + rbase + 32;  b = g / NS; s = g - b * NS;
        gp1 = kg + ((size_t)(b * NF + f) * NS + s) * 16 + c4l;
        g = g0 + rbase + 64;  b = g / NS; s = g - b * NS;
        gp2 = kg + ((size_t)(b * NF + f) * NS + s) * 16 + c4l;
        g = g0 + rbase + 96;  b = g / NS; s = g - b * NS;
        gp3 = kg + ((size_t)(b * NF + f) * NS + s) * 16 + c4l;
    }

    // prefetch chunk 0
    float4 pf0 = gp0[0], pf1 = gp1[0], pf2 = gp2[0], pf3 = gp3[0];

    __syncthreads();   // A_s + qh_sm visible

    // acc init with qh
    unsigned long long acc[4][4];
    float acc8[4];
    #pragma unroll
    for (int j4 = 0; j4 < 4; ++j4) {
        int bsel = ((g0 + l + 32 * j4) >= (b0 + 1) * NS) ? 1 : 0;
        const float* qh = qh_sm + bsel * 40 + wq * 10;
        #pragma unroll
        for (int c = 0; c < 4; ++c)
            acc[j4][c] = *(const unsigned long long*)(qh + 2 * c);
        acc8[j4] = qh[8];
    }

    const float* abase = A_s + wq * 12;

    #pragma unroll
    for (int ch = 0; ch < 4; ++ch) {
        float* kb = (ch & 1) ? kt1 : kt0;
        // STS current chunk (transposed)
        {
            float* d0 = kb + (c4l * 4) * KTP;
            d0[0 * KTP + rbase]      = pf0.x;  d0[1 * KTP + rbase]      = pf0.y;
            d0[2 * KTP + rbase]      = pf0.z;  d0[3 * KTP + rbase]      = pf0.w;
            d0[0 * KTP + rbase + 32] = pf1.x;  d0[1 * KTP + rbase + 32] = pf1.y;
            d0[2 * KTP + rbase + 32] = pf1.z;  d0[3 * KTP + rbase + 32] = pf1.w;
            d0[0 * KTP + rbase + 64] = pf2.x;  d0[1 * KTP + rbase + 64] = pf2.y;
            d0[2 * KTP + rbase + 64] = pf2.z;  d0[3 * KTP + rbase + 64] = pf2.w;
            d0[0 * KTP + rbase + 96] = pf3.x;  d0[1 * KTP + rbase + 96] = pf3.y;
            d0[2 * KTP + rbase + 96] = pf3.z;  d0[3 * KTP + rbase + 96] = pf3.w;
        }
        // prefetch next chunk (overlaps with this chunk's FMAs)
        if (ch < 3) {
            pf0 = gp0[(ch + 1) * 4];
            pf1 = gp1[(ch + 1) * 4];
            pf2 = gp2[(ch + 1) * 4];
            pf3 = gp3[(ch + 1) * 4];
        }
        __syncthreads();

        const float* ach = abase + ch * KCH * 48;
        const float* kcb = kb + l;
        #pragma unroll 4
        for (int kl = 0; kl < KCH; ++kl) {
            const float* ar = ach + kl * 48;
            F4U2 u0; u0.f4 = *(const float4*)(ar);       // a0..a3
            F4U2 u1; u1.f4 = *(const float4*)(ar + 4);   // a4..a7
            float a8 = ar[8];
            const float* kc = kcb + kl * KTP;
            float kv0 = kc[0], kv1 = kc[32], kv2 = kc[64], kv3 = kc[96];
            {
                unsigned long long kk = pack2(kv0);
                fma2(acc[0][0], u0.u2.x, kk); fma2(acc[0][1], u0.u2.y, kk);
                fma2(acc[0][2], u1.u2.x, kk); fma2(acc[0][3], u1.u2.y, kk);
                acc8[0] = fmaf(a8, kv0, acc8[0]);
            }
            {
                unsigned long long kk = pack2(kv1);
                fma2(acc[1][0], u0.u2.x, kk); fma2(acc[1][1], u0.u2.y, kk);
                fma2(acc[1][2], u1.u2.x, kk); fma2(acc[1][3], u1.u2.y, kk);
                acc8[1] = fmaf(a8, kv1, acc8[1]);
            }
            {
                unsigned long long kk = pack2(kv2);
                fma2(acc[2][0], u0.u2.x, kk); fma2(acc[2][1], u0.u2.y, kk);
                fma2(acc[2][2], u1.u2.x, kk); fma2(acc[2][3], u1.u2.y, kk);
                acc8[2] = fmaf(a8, kv2, acc8[2]);
            }
            {
                unsigned long long kk = pack2(kv3);
                fma2(acc[3][0], u0.u2.x, kk); fma2(acc[3][1], u0.u2.y, kk);
                fma2(acc[3][2], u1.u2.x, kk); fma2(acc[3][3], u1.u2.y, kk);
                acc8[3] = fmaf(a8, kv3, acc8[3]);
            }
        }
    }
    __syncthreads();   // all FMA done -> safe to overlay h_st

    // epilogue: store h + per-column partials in registers
    const int jc = wq * 9;
    float cs[9], cq[9];
    #pragma unroll
    for (int c = 0; c < 9; ++c) { cs[c] = 0.0f; cq[c] = 0.0f; }
    #pragma unroll
    for (int j4 = 0; j4 < 4; ++j4) {
        int r = l + 32 * j4;
        float* hr = h_st + r * HPAD + jc;
        #pragma unroll
        for (int c = 0; c < 4; ++c) {
            F2U1 u; u.u = acc[j4][c];
            float h0 = u.f2.x, h1 = u.f2.y;
            hr[2 * c] = h0; hr[2 * c + 1] = h1;
            cs[2 * c]     += h0; cq[2 * c]     = fmaf(h0, h0, cq[2 * c]);
            cs[2 * c + 1] += h1; cq[2 * c + 1] = fmaf(h1, h1, cq[2 * c + 1]);
        }
        float h8 = acc8[j4];
        hr[8] = h8;
        cs[8] += h8; cq[8] = fmaf(h8, h8, cq[8]);
    }
    #pragma unroll
    for (int m = 16; m > 0; m >>= 1) {
        #pragma unroll
        for (int c = 0; c < 9; ++c) {
            cs[c] += __shfl_xor_sync(0xffffffffu, cs[c], m);
            cq[c] += __shfl_xor_sync(0xffffffffu, cq[c], m);
        }
    }
    if (l == 0) {
        #pragma unroll
        for (int c = 0; c < 9; ++c) {
            g_psum[blockIdx.x * NH + jc + c] = cs[c];
            g_psq [blockIdx.x * NH + jc + c] = cq[c];
        }
    }
    __syncthreads();

    // fp16 copy-out: 2304 half2 over 128 threads
    #pragma unroll
    for (int it = 0; it < 18; ++it) {
        int i = t + it * P1T;           // 0..2303
        int row = i / 18, e = i - row * 18;
        int gg = g0 + row;
        int b = gg / NS, s = gg - b * NS;
        float2 v = *(const float2*)(h_st + row * HPAD + 2 * e);
        g_h[((size_t)(b * NF + f) * NS + s) * 18 + e] = __float22half2_rn(v);
    }
}

// ---------------------------------------------------------------------------
// Stats finalize: reduce 400 tile-partials per (f,j)
// ---------------------------------------------------------------------------
__global__ void __launch_bounds__(256) kstats_kernel()
{
    __shared__ float rs[256], rq[256];
    const int col = blockIdx.x;           // f*36 + j
    const int f = col / NH, j = col - f * NH;
    const int t = threadIdx.x;
    float ss = 0.f, qq = 0.f;
    for (int i = t; i < NTILES; i += 256) {
        ss += g_psum[(f * NTILES + i) * NH + j];
        qq += g_psq [(f * NTILES + i) * NH + j];
    }
    rs[t] = ss; rq[t] = qq;
    __syncthreads();
    for (int off = 128; off > 0; off >>= 1) {
        if (t < off) { rs[t] += rs[t + off]; rq[t] += rq[t + off]; }
        __syncthreads();
    }
    if (t == 0) {
        const float invN = 1.0f / (float)(NB * NS);
        float mean = rs[0] * invN;
        float var  = rq[0] * invN - mean * mean;
        g_mean[col] = mean;
        g_inv[col]  = rsqrtf(var + EPS_V);
    }
}

// ---------------------------------------------------------------------------
// Pass 3: gate + scores + masked softmax + attn @ key.
// h row via LDS.128; attn loop 2-way unrolled (MLP=2); shfl reductions.
// ---------------------------------------------------------------------------
__global__ void __launch_bounds__(256) pass3_kernel(
    const float* __restrict__ key, const float* __restrict__ alpha,
    const float* __restrict__ W_o, const float* __restrict__ b_o,
    const int* __restrict__ seqnum, float* __restrict__ out)
{
    __shared__ float h_sm[NS * NH];
    __shared__ float inv_s[NH], nm_s[NH], wo_s[NH];
    __shared__ float sc[NS];
    __shared__ float red[16];
    __shared__ float opart[256];

    const int tid = threadIdx.x;
    const int wid = tid >> 5, lid = tid & 31;
    const int bf  = blockIdx.x;
    const int f   = bf & 7;
    const int n   = seqnum[bf];

    {
        const __half2* hg = g_h + (size_t)bf * (NS * NH / 2);
        const int tot = n * 18;      // only live rows
        for (int i = tid; i < tot; i += 256)
            ((float2*)h_sm)[i] = __half22float2(hg[i]);
    }
    if (tid < NH) {
        float m  = g_mean[f * NH + tid];
        float iv = g_inv [f * NH + tid];
        inv_s[tid] = iv;
        nm_s[tid]  = -m * iv;
        wo_s[tid]  = W_o[f * NH + tid];
    }
    const float al  = alpha[f];
    const float oma = 1.0f - al;
    __syncthreads();

    float score = -3.0e38f;
    if (tid < n) {
        float s = b_o[f];
        const float4* h4 = (const float4*)(h_sm + tid * NH);   // 144B-aligned
        #pragma unroll
        for (int jq = 0; jq < 9; ++jq) {
            float4 hv = h4[jq];
            const float hvv[4] = {hv.x, hv.y, hv.z, hv.w};
            #pragma unroll
            for (int e = 0; e < 4; ++e) {
                int j = jq * 4 + e;
                float v = hvv[e];
                float z = fmaf(v, inv_s[j], nm_s[j]);
                float p = fast_sigmoid(z);
                float g = fmaf(oma, p, al) * v;
                s = fmaf(g, wo_s[j], s);
            }
        }
        score = s;
    }
    // warp max -> 8 partials -> local max
    float mv = score;
    #pragma unroll
    for (int m = 16; m > 0; m >>= 1)
        mv = fmaxf(mv, __shfl_xor_sync(0xffffffffu, mv, m));
    if (lid == 0) red[wid] = mv;
    __syncthreads();
    float mx = red[0];
    #pragma unroll
    for (int w = 1; w < 8; ++w) mx = fmaxf(mx, red[w]);

    float e = 0.0f;
    if (tid < n) {
        e = __expf(score - mx);
        sc[tid] = e;
    }
    float sv = e;
    #pragma unroll
    for (int m = 16; m > 0; m >>= 1)
        sv += __shfl_xor_sync(0xffffffffu, sv, m);
    if (lid == 0) red[8 + wid] = sv;
    __syncthreads();   // also publishes sc[]
    float denom = red[8];
    #pragma unroll
    for (int w = 1; w < 8; ++w) denom += red[8 + w];

    const int d = tid & 63;
    const int g = tid >> 6;
    const float* kb = key + (size_t)bf * (NS * ND);
    float a0 = 0.0f, a1 = 0.0f;
    int s = g;
    for (; s + 4 < n; s += 8) {
        a0 = fmaf(sc[s],     kb[s * ND + d],       a0);
        a1 = fmaf(sc[s + 4], kb[(s + 4) * ND + d], a1);
    }
    if (s < n) a0 = fmaf(sc[s], kb[s * ND + d], a0);
    opart[tid] = a0 + a1;
    __syncthreads();
    if (tid < ND) {
        float o = opart[tid] + opart[tid + 64] + opart[tid + 128] + opart[tid + 192];
        out[(size_t)bf * ND + tid] = o / denom;
    }
}

// ---------------------------------------------------------------------------
extern "C" void kernel_launch(void* const* d_in, const int* in_sizes, int n_in,
                              void* d_out, int out_size)
{
    const float* q      = (const float*)d_in[0];
    const float* key    = (const float*)d_in[1];
    const float* W_h    = (const float*)d_in[2];
    const float* b_h    = (const float*)d_in[3];
    const float* alpha  = (const float*)d_in[4];
    const float* W_o    = (const float*)d_in[5];
    const float* b_o    = (const float*)d_in[6];
    const int*   seqn   = (const int*)d_in[7];
    float* out = (float*)d_out;

    cudaFuncSetAttribute(pass1_kernel,
                         cudaFuncAttributeMaxDynamicSharedMemorySize,
                         P1_SMEM_BYTES);

    prep_kernel<<<NBF + NF, 256>>>(q, W_h, b_h);
    pass1_kernel<<<P1GRID, P1T, P1_SMEM_BYTES>>>(key);
    kstats_kernel<<<NSTAT, 256>>>();
    pass3_kernel<<<NBF, 256>>>(key, alpha, W_o, b_o, seqn, out);
}